// round 7
// baseline (speedup 1.0000x reference)
#include <cuda_runtime.h>
#include <cuda_bf16.h>
#include <math_constants.h>
#include <cstdint>

#define BB    64
#define TT    2048
#define DRNN  1024
#define DEMB  512
#define DATT  128
#define NF    32
#define KS    31
#define PADW  15
#define NSPLIT 32
#define LOCS  36
// s_pm: [4 t-quarters][2 bufs][4 t][128 a]
#define PM_STAGE_T 4
#define PM_BUF_FLOATS (PM_STAGE_T * 128)         // 512
#define PM_TQ_FLOATS  (2 * PM_BUF_FLOATS)        // 1024

// ---------------- device scratch ----------------
__device__ float  g_pq[BB * DATT];
__device__ float2 g_cw2[62 * 16];
__device__ float  g_energy[BB * TT];
__device__ float  g_ctx_part[NSPLIT * BB * DEMB];

typedef unsigned long long ull;

// ---------------- helpers ----------------
__device__ __forceinline__ ull ffma2u(ull a, ull b, ull c) {
    ull d;
    asm("fma.rn.f32x2 %0, %1, %2, %3;" : "=l"(d) : "l"(a), "l"(b), "l"(c));
    return d;
}
__device__ __forceinline__ ull add2u(ull a, ull b) {
    ull d;
    asm("add.rn.f32x2 %0, %1, %2;" : "=l"(d) : "l"(a), "l"(b));
    return d;
}
__device__ __forceinline__ ull pack2(float x, float y) {
    ull r; asm("mov.b64 %0, {%1, %2};" : "=l"(r) : "f"(x), "f"(y)); return r;
}
__device__ __forceinline__ float2 unpack2(ull v) {
    float2 f; asm("mov.b64 {%0, %1}, %2;" : "=f"(f.x), "=f"(f.y) : "l"(v)); return f;
}
__device__ __forceinline__ float tanh_fast(float x) {
    float y; asm("tanh.approx.f32 %0, %1;" : "=f"(y) : "f"(x)); return y;
}
__device__ __forceinline__ void cp_async8(uint32_t dst, const void* src) {
    asm volatile("cp.async.ca.shared.global [%0], [%1], 8;" :: "r"(dst), "l"(src));
}

// ---------------- K0: pq GEMM (4x parallel) + conv weight repacking ----------------
__global__ __launch_bounds__(128) void prep_kernel(
    const float* __restrict__ hidden, const float* __restrict__ Wq,
    const float* __restrict__ convw)
{
    __shared__ float s_h[DRNN];
    int tid = threadIdx.x, b = blockIdx.x, slice = blockIdx.y;
    for (int i = tid; i < DRNN; i += 128) s_h[i] = hidden[(size_t)b * DRNN + i];
    __syncthreads();

    int w = tid >> 5, lane = tid & 31;
    #pragma unroll
    for (int i = 0; i < 8; i++) {
        int a = slice * 32 + w * 8 + i;
        const float* wq = Wq + (size_t)a * DRNN;
        float acc0 = 0.f, acc1 = 0.f;
        #pragma unroll 4
        for (int k = lane; k < DRNN; k += 64) {
            acc0 = fmaf(s_h[k],      wq[k],      acc0);
            acc1 = fmaf(s_h[k + 32], wq[k + 32], acc1);
        }
        float acc = acc0 + acc1;
        #pragma unroll
        for (int off = 16; off; off >>= 1) acc += __shfl_down_sync(0xffffffffu, acc, off);
        if (lane == 0) g_pq[b * DATT + a] = acc;
    }

    if (b == 0 && slice == 0) {
        for (int i = tid; i < 62 * 16; i += 128) {
            int ck = i >> 4, fp = i & 15;
            g_cw2[i] = make_float2(convw[(2 * fp) * 62 + ck], convw[(2 * fp + 1) * 62 + ck]);
        }
    }
}

__global__ void dummy_kernel() {}

// ---------------- K1: conv + paw + tanh + v-dot -> energies ----------------
// 256 threads = 8 warps. Warp w = (tq = w>>1 : t-quarter of 32, aj = w&1 : a-half).
// Lane owns a-pair a0 = aj*64 + 2*lane; Wd rows a0,a0+1 (64 regs) register-resident.
// Conv split across fh-halves: thread (t = tid&127, fh = tid>>7) computes 16 filters.
__global__ __launch_bounds__(256, 3) void energy_kernel(
    const float* __restrict__ pm, const float* __restrict__ aw,
    const float* __restrict__ wv, const float* __restrict__ Wd)
{
    __shared__ __align__(16) float s_aw[2 * 160];
    __shared__ __align__(16) float s_cw[62 * 32];
    __shared__ __align__(16) float s_loc[128 * LOCS];
    __shared__ float s_red[128 * 2];
    __shared__ __align__(16) float s_pm[4 * PM_TQ_FLOATS];   // 16 KB

    int tid = threadIdx.x;
    int b   = blockIdx.y;
    int t0  = blockIdx.x * 128;
    int w   = tid >> 5, lane = tid & 31;
    const int tq = w >> 1, aj = w & 1;
    const int a0 = aj * 64 + 2 * lane;

    // ---- pm pipeline: warp (tq,aj) stages its own a-half for its 32 t's ----
    const float* pmB = pm + ((size_t)b * TT + t0 + tq * 32) * DATT + a0;
    uint32_t pmS = (uint32_t)__cvta_generic_to_shared(s_pm)
                 + (tq * PM_TQ_FLOATS + a0) * 4;

    #define ISSUE_STAGE(sg) do {                                              \
        uint32_t dstb = pmS + (((sg) & 1) ? (PM_BUF_FLOATS * 4) : 0);         \
        const float* srcb = pmB + (size_t)(sg) * PM_STAGE_T * DATT;           \
        _Pragma("unroll")                                                     \
        for (int t_ = 0; t_ < PM_STAGE_T; t_++)                               \
            cp_async8(dstb + t_ * (128 * 4), srcb + (size_t)t_ * DATT);       \
        asm volatile("cp.async.commit_group;" ::: "memory");                  \
    } while (0)

    ISSUE_STAGE(0);
    ISSUE_STAGE(1);

    // ---- stage conv inputs ----
    const float* awB = aw + (size_t)b * 2 * TT;
    for (int i = tid; i < 2 * 158; i += 256) {
        int c = i / 158, j = i - c * 158;
        int tg = t0 + j - PADW;
        s_aw[c * 160 + j] = (tg >= 0 && tg < TT) ? awB[(size_t)c * TT + tg] : 0.f;
    }
    {
        const float4* src = (const float4*)g_cw2;
        float4* dst = (float4*)s_cw;
        for (int i = tid; i < 496; i += 256) dst[i] = src[i];
    }
    __syncthreads();

    // ---- conv: thread (t = tid&127, fh = tid>>7) -> loc[t][fh*16 .. fh*16+16) ----
    {
        const int tloc = tid & 127, fh = tid >> 7;
        ull acc[8];
        #pragma unroll
        for (int i = 0; i < 8; i++) acc[i] = 0ULL;
        #pragma unroll 2
        for (int ck = 0; ck < 62; ck++) {
            int c = (ck >= 31), k = ck - c * 31;
            float av = s_aw[c * 160 + tloc + k];
            ull av2 = pack2(av, av);
            const ulonglong2* row = (const ulonglong2*)(s_cw + ck * 32 + fh * 16);
            #pragma unroll
            for (int q = 0; q < 4; q++) {
                ulonglong2 w2 = row[q];
                acc[2 * q]     = ffma2u(av2, w2.x, acc[2 * q]);
                acc[2 * q + 1] = ffma2u(av2, w2.y, acc[2 * q + 1]);
            }
        }
        #pragma unroll
        for (int i = 0; i < 8; i++) {
            float2 a2 = unpack2(acc[i]);
            *(float2*)(s_loc + tloc * LOCS + fh * 16 + 2 * i) = a2;
        }
    }
    __syncthreads();

    // ---- per-thread params (loaded after conv to limit register peak) ----
    float2 pq2 = *(const float2*)(g_pq + b * DATT + a0);
    float2 wv2 = *(const float2*)(wv + a0);
    ull wp[32];                                   // Wd rows a0, a0+1
    {
        const ull* src = (const ull*)(Wd + (size_t)a0 * NF);
        #pragma unroll
        for (int i = 0; i < 32; i++) wp[i] = src[i];
    }

    // ---- main loop: warp's 32 t's in 8 stages of 4 ----
    const float* locBase = s_loc + tq * 32 * LOCS;
    for (int sg = 0; sg < 8; sg++) {
        asm volatile("cp.async.wait_group 1;" ::: "memory");
        const float* pbuf  = s_pm + tq * PM_TQ_FLOATS + (sg & 1) * PM_BUF_FLOATS;
        const float* lrowB = locBase + sg * PM_STAGE_T * LOCS;

        #pragma unroll
        for (int tl = 0; tl < PM_STAGE_T; tl++) {
            float2 pmv = *(const float2*)(pbuf + tl * 128 + a0);
            const ulonglong2* lrow = (const ulonglong2*)(lrowB + tl * LOCS);
            ull a0c = 0ULL, a1c = 0ULL, b0c = 0ULL, b1c = 0ULL;
            #pragma unroll
            for (int q = 0; q < 8; q++) {
                ulonglong2 l = lrow[q];
                a0c = ffma2u(l.x, wp[2 * q],          a0c);
                a1c = ffma2u(l.y, wp[2 * q + 1],      a1c);
                b0c = ffma2u(l.x, wp[16 + 2 * q],     b0c);
                b1c = ffma2u(l.y, wp[16 + 2 * q + 1], b1c);
            }
            float2 pa = unpack2(add2u(a0c, a1c));
            float2 pb = unpack2(add2u(b0c, b1c));
            float x0 = pq2.x + pmv.x + (pa.x + pa.y);
            float x1 = pq2.y + pmv.y + (pb.x + pb.y);
            float c = fmaf(wv2.x, tanh_fast(x0), wv2.y * tanh_fast(x1));
            #pragma unroll
            for (int off = 16; off; off >>= 1) c += __shfl_xor_sync(0xffffffffu, c, off);
            if (lane == 0) s_red[(tq * 32 + sg * PM_STAGE_T + tl) * 2 + aj] = c;
        }
        if (sg < 6) { ISSUE_STAGE(sg + 2); }
        else        { asm volatile("cp.async.commit_group;" ::: "memory"); }
    }
    __syncthreads();

    if (tid < 128) {
        float e = s_red[tid * 2] + s_red[tid * 2 + 1];
        g_energy[(size_t)b * TT + t0 + tid] = e;
    }
}

// ---------------- K2: masked softmax (mask = int32) ----------------
__global__ __launch_bounds__(256) void softmax_kernel(
    const int* __restrict__ mask, float* __restrict__ out_w)
{
    __shared__ float red[32];
    int tid = threadIdx.x, b = blockIdx.x;
    float vals[8];
    float mx = -CUDART_INF_F;
    #pragma unroll
    for (int j = 0; j < 8; j++) {
        int t = tid + j * 256;
        float e = g_energy[(size_t)b * TT + t];
        float v = (mask[(size_t)b * TT + t] != 0) ? -CUDART_INF_F : e;
        vals[j] = v;
        mx = fmaxf(mx, v);
    }
    #pragma unroll
    for (int off = 16; off; off >>= 1) mx = fmaxf(mx, __shfl_xor_sync(0xffffffffu, mx, off));
    if ((tid & 31) == 0) red[tid >> 5] = mx;
    __syncthreads();
    if (tid < 32) {
        float m = (tid < 8) ? red[tid] : -CUDART_INF_F;
        #pragma unroll
        for (int off = 4; off; off >>= 1) m = fmaxf(m, __shfl_xor_sync(0xffffffffu, m, off));
        red[tid] = m;
    }
    __syncthreads();
    mx = red[0];

    float s = 0.f;
    #pragma unroll
    for (int j = 0; j < 8; j++) { float ev = __expf(vals[j] - mx); vals[j] = ev; s += ev; }
    #pragma unroll
    for (int off = 16; off; off >>= 1) s += __shfl_xor_sync(0xffffffffu, s, off);
    __syncthreads();
    if ((tid & 31) == 0) red[tid >> 5] = s;
    __syncthreads();
    if (tid < 32) {
        float m = (tid < 8) ? red[tid] : 0.f;
        #pragma unroll
        for (int off = 4; off; off >>= 1) m += __shfl_xor_sync(0xffffffffu, m, off);
        red[tid] = m;
    }
    __syncthreads();
    float inv = 1.f / red[0];
    #pragma unroll
    for (int j = 0; j < 8; j++) out_w[(size_t)b * TT + tid + j * 256] = vals[j] * inv;
}

// ---------------- K3: context partials ----------------
__global__ __launch_bounds__(128) void context_kernel(
    const float* __restrict__ memory, const float* __restrict__ wgt)
{
    __shared__ float s_w[64];
    int tid = threadIdx.x;
    int b = blockIdx.y, ts = blockIdx.x;
    int t0 = ts * 64;
    if (tid < 64) s_w[tid] = wgt[(size_t)b * TT + t0 + tid];
    __syncthreads();

    const float4* m4 = (const float4*)(memory + ((size_t)b * TT + t0) * DEMB) + tid;
    float4 acc = make_float4(0.f, 0.f, 0.f, 0.f);
    for (int i = 0; i < 64; i += 8) {
        float4 v[8];
        #pragma unroll
        for (int u = 0; u < 8; u++) v[u] = m4[(size_t)(i + u) * 128];
        #pragma unroll
        for (int u = 0; u < 8; u++) {
            float w = s_w[i + u];
            acc.x = fmaf(w, v[u].x, acc.x);
            acc.y = fmaf(w, v[u].y, acc.y);
            acc.z = fmaf(w, v[u].z, acc.z);
            acc.w = fmaf(w, v[u].w, acc.w);
        }
    }
    ((float4*)g_ctx_part)[(size_t)ts * (BB * DEMB / 4) + b * (DEMB / 4) + tid] = acc;
}

// ---------------- K4: reduce context partials ----------------
__global__ __launch_bounds__(256) void reduce_kernel(float* __restrict__ out_ctx)
{
    int i = blockIdx.x * 256 + threadIdx.x;
    float s = 0.f;
    #pragma unroll
    for (int ts = 0; ts < NSPLIT; ts++) s += g_ctx_part[(size_t)ts * BB * DEMB + i];
    out_ctx[i] = s;
}

// ---------------- launch ----------------
extern "C" void kernel_launch(void* const* d_in, const int* in_sizes, int n_in,
                              void* d_out, int out_size)
{
    const float* hidden = (const float*)d_in[0];
    const float* memory = (const float*)d_in[1];
    const float* pm     = (const float*)d_in[2];
    const float* awc    = (const float*)d_in[3];
    const int*   mask   = (const int*)d_in[4];
    const float* Wq     = (const float*)d_in[5];
    const float* Wv     = (const float*)d_in[6];
    const float* convw  = (const float*)d_in[7];
    const float* Wd     = (const float*)d_in[8];

    float* out     = (float*)d_out;
    float* out_ctx = out;                  // [B, 512]
    float* out_w   = out + BB * DEMB;      // [B, T]

    prep_kernel<<<dim3(64, 4), 128>>>(hidden, Wq, convw);
    dummy_kernel<<<1, 32>>>();
    dummy_kernel<<<1, 32>>>();
    energy_kernel<<<dim3(16, 64), 256>>>(pm, awc, Wv, Wd);
    softmax_kernel<<<64, 256>>>(mask, out_w);
    context_kernel<<<dim3(NSPLIT, 64), 128>>>(memory, out_w);
    reduce_kernel<<<128, 256>>>(out_ctx);
}

// round 9
// speedup vs baseline: 1.0750x; 1.0750x over previous
#include <cuda_runtime.h>
#include <cuda_bf16.h>
#include <math_constants.h>
#include <cstdint>

#define BB    64
#define TT    2048
#define DRNN  1024
#define DEMB  512
#define DATT  128
#define NF    32
#define KS    31
#define PADW  15
#define NSPLIT 32

// bf16 image rows padded to 104 elems = 208 bytes (16B aligned, LDSM conflict-free)
#define KPAD   104
#define ROWB   208

// ---- energy kernel dynamic smem layout (bytes) ----
#define SM_B     0                         // Wd image: 128 x 208 B = 26624
#define SM_LOCB  26624                     // loc bf16: 128 x 208 B = 26624
#define SM_AW    53248                     // 2*160 floats = 1280
#define SM_CW    54528                     // 62*32 floats = 7936
#define SM_PQ    62464                     // 128 floats
#define SM_WV    62976                     // 128 floats
#define SM_E     63488                     // 128 floats
#define SM_TOTAL 64000

// ---------------- device scratch ----------------
__device__ float  g_pq[BB * DATT];
__device__ float2 g_cw2[62 * 16];
__device__ unsigned short g_wdbp[128 * KPAD];  // B image [a][k] bf16: Wh|Wh|Wl|0pad
__device__ float  g_energy[BB * TT];
__device__ float  g_ctx_part[NSPLIT * BB * DEMB];

typedef unsigned long long ull;

// ---------------- helpers ----------------
__device__ __forceinline__ ull ffma2u(ull a, ull b, ull c) {
    ull d;
    asm("fma.rn.f32x2 %0, %1, %2, %3;" : "=l"(d) : "l"(a), "l"(b), "l"(c));
    return d;
}
__device__ __forceinline__ ull pack2(float x, float y) {
    ull r; asm("mov.b64 %0, {%1, %2};" : "=l"(r) : "f"(x), "f"(y)); return r;
}
__device__ __forceinline__ float2 unpack2(ull v) {
    float2 f; asm("mov.b64 {%0, %1}, %2;" : "=f"(f.x), "=f"(f.y) : "l"(v)); return f;
}
__device__ __forceinline__ float tanh_fast(float x) {
    float y; asm("tanh.approx.f32 %0, %1;" : "=f"(y) : "f"(x)); return y;
}
__device__ __forceinline__ uint32_t smem_u32(const void* p) {
    uint32_t a;
    asm("{ .reg .u64 t; cvta.to.shared.u64 t, %1; cvt.u32.u64 %0, t; }" : "=r"(a) : "l"(p));
    return a;
}
__device__ __forceinline__ void ldsm4(uint32_t* r, uint32_t addr) {
    asm volatile("ldmatrix.sync.aligned.m8n8.x4.shared.b16 {%0,%1,%2,%3}, [%4];"
        : "=r"(r[0]), "=r"(r[1]), "=r"(r[2]), "=r"(r[3]) : "r"(addr));
}
__device__ __forceinline__ void mma_bf16(float* d, const uint32_t* a,
                                         uint32_t b0, uint32_t b1) {
    asm volatile("mma.sync.aligned.m16n8k16.row.col.f32.bf16.bf16.f32 "
        "{%0,%1,%2,%3}, {%4,%5,%6,%7}, {%8,%9}, {%0,%1,%2,%3};"
        : "+f"(d[0]), "+f"(d[1]), "+f"(d[2]), "+f"(d[3])
        : "r"(a[0]), "r"(a[1]), "r"(a[2]), "r"(a[3]), "r"(b0), "r"(b1));
}

// ---------------- K0: pq GEMM + conv repack + Wd bf16 image ----------------
__global__ __launch_bounds__(128) void prep_kernel(
    const float* __restrict__ hidden, const float* __restrict__ Wq,
    const float* __restrict__ convw,  const float* __restrict__ Wd)
{
    __shared__ float s_h[DRNN];
    int tid = threadIdx.x, b = blockIdx.x, slice = blockIdx.y;
    for (int i = tid; i < DRNN; i += 128) s_h[i] = hidden[(size_t)b * DRNN + i];
    __syncthreads();

    int w = tid >> 5, lane = tid & 31;
    #pragma unroll
    for (int i = 0; i < 8; i++) {
        int a = slice * 32 + w * 8 + i;
        const float* wq = Wq + (size_t)a * DRNN;
        float acc0 = 0.f, acc1 = 0.f;
        #pragma unroll 4
        for (int k = lane; k < DRNN; k += 64) {
            acc0 = fmaf(s_h[k],      wq[k],      acc0);
            acc1 = fmaf(s_h[k + 32], wq[k + 32], acc1);
        }
        float acc = acc0 + acc1;
        #pragma unroll
        for (int off = 16; off; off >>= 1) acc += __shfl_down_sync(0xffffffffu, acc, off);
        if (lane == 0) g_pq[b * DATT + a] = acc;
    }

    if (b == 0 && slice == 0) {
        for (int i = tid; i < 62 * 16; i += 128) {
            int ck = i >> 4, fp = i & 15;
            g_cw2[i] = make_float2(convw[(2 * fp) * 62 + ck], convw[(2 * fp + 1) * 62 + ck]);
        }
        // B image rows [a][k]: k<64: Wh[k&31]; k<96: Wl[k-64]; else 0
        for (int i = tid; i < 128 * KPAD; i += 128) {
            int a = i / KPAD, k = i - a * KPAD;
            __nv_bfloat16 bv = __float2bfloat16(0.f);
            if (k < 64) {
                bv = __float2bfloat16(Wd[a * NF + (k & 31)]);
            } else if (k < 96) {
                float orig = Wd[a * NF + (k - 64)];
                float hi = __bfloat162float(__float2bfloat16(orig));
                bv = __float2bfloat16(orig - hi);
            }
            g_wdbp[i] = *(unsigned short*)&bv;
        }
    }
}

__global__ void dummy_kernel() {}

// ---------------- K1: conv + mma.sync paw + tanh + v-dot -> energies ----------------
// 128 threads = 4 warps. Warp w owns t rows tb=32w..tb+31, all 128 a (two n-halves).
__global__ __launch_bounds__(128) void energy_kernel(
    const float* __restrict__ pm, const float* __restrict__ aw,
    const float* __restrict__ wv)
{
    extern __shared__ __align__(16) char smc[];
    float* s_aw = (float*)(smc + SM_AW);
    float* s_cw = (float*)(smc + SM_CW);
    float* s_pq = (float*)(smc + SM_PQ);
    float* s_wv = (float*)(smc + SM_WV);
    float* s_e  = (float*)(smc + SM_E);

    int tid = threadIdx.x;
    int b   = blockIdx.y;
    int t0  = blockIdx.x * 128;
    int w   = tid >> 5, lane = tid & 31;
    const int tb = w * 32;
    uint32_t sbase = smem_u32(smc);

    // ---- stage: B image, conv inputs, pq, wv ----
    {
        const float4* src = (const float4*)g_wdbp;     // 1664 float4
        float4* dst = (float4*)(smc + SM_B);
        for (int i = tid; i < 1664; i += 128) dst[i] = src[i];
    }
    const float* awB = aw + (size_t)b * 2 * TT;
    for (int i = tid; i < 2 * 158; i += 128) {
        int c = i / 158, j = i - c * 158;
        int tg = t0 + j - PADW;
        s_aw[c * 160 + j] = (tg >= 0 && tg < TT) ? awB[(size_t)c * TT + tg] : 0.f;
    }
    {
        const float4* src = (const float4*)g_cw2;      // 496 float4
        float4* dst = (float4*)s_cw;
        for (int i = tid; i < 496; i += 128) dst[i] = src[i];
    }
    s_pq[tid] = g_pq[b * DATT + tid];
    s_wv[tid] = wv[tid];
    __syncthreads();

    // ---- conv: thread tid -> loc[t0+tid][32 f] fp32 ----
    ull cacc[16];
    #pragma unroll
    for (int fp = 0; fp < 16; fp++) cacc[fp] = 0ULL;
    #pragma unroll 2
    for (int ck = 0; ck < 62; ck++) {
        int c = (ck >= 31), k = ck - c * 31;
        float av = s_aw[c * 160 + tid + k];
        ull av2 = pack2(av, av);
        const ulonglong2* row = (const ulonglong2*)(s_cw + ck * 32);
        #pragma unroll
        for (int q = 0; q < 8; q++) {
            ulonglong2 w2 = row[q];
            cacc[2 * q]     = ffma2u(av2, w2.x, cacc[2 * q]);
            cacc[2 * q + 1] = ffma2u(av2, w2.y, cacc[2 * q + 1]);
        }
    }

    // ---- hi/lo split -> s_locb row (k: hi[0..31] | lo[32..63] | hi[64..95]) ----
    {
        uint32_t awords[48];
        #pragma unroll
        for (int fp = 0; fp < 16; fp++) {
            float2 v = unpack2(cacc[fp]);
            __nv_bfloat16 h0 = __float2bfloat16(v.x), h1 = __float2bfloat16(v.y);
            float r0 = v.x - __bfloat162float(h0);
            float r1 = v.y - __bfloat162float(h1);
            __nv_bfloat16 l0 = __float2bfloat16(r0), l1 = __float2bfloat16(r1);
            uint32_t hw = ((uint32_t)__bfloat16_as_ushort(h1) << 16) | __bfloat16_as_ushort(h0);
            uint32_t lw = ((uint32_t)__bfloat16_as_ushort(l1) << 16) | __bfloat16_as_ushort(l0);
            awords[fp]      = hw;
            awords[16 + fp] = lw;
            awords[32 + fp] = hw;
        }
        uint4* dst = (uint4*)(smc + SM_LOCB + tid * ROWB);
        #pragma unroll
        for (int j = 0; j < 12; j++)
            dst[j] = make_uint4(awords[4 * j], awords[4 * j + 1],
                                awords[4 * j + 2], awords[4 * j + 3]);
    }
    __syncwarp();   // warp w's A rows (tb..tb+31) are written by warp w's own threads

    // ---- per-warp MMA + epilogue ----
    const uint32_t sLocb = sbase + SM_LOCB;
    const uint32_t sBimg = sbase + SM_B;
    const float* pmBase = pm + ((size_t)b * TT + t0) * DATT;

    float es00 = 0.f, es01 = 0.f, es10 = 0.f, es11 = 0.f;

    #pragma unroll
    for (int nh = 0; nh < 2; nh++) {
        float acc[2][8][4];
        #pragma unroll
        for (int mt = 0; mt < 2; mt++)
            #pragma unroll
            for (int nt = 0; nt < 8; nt++)
                #pragma unroll
                for (int q = 0; q < 4; q++) acc[mt][nt][q] = 0.f;

        #pragma unroll
        for (int ks = 0; ks < 6; ks++) {
            const int kk = ks * 16;
            uint32_t af[2][4];
            uint32_t abase = sLocb + (tb + (lane & 15)) * ROWB
                           + (kk + (lane >> 4) * 8) * 2;
            ldsm4(af[0], abase);
            ldsm4(af[1], abase + 16 * ROWB);
            uint32_t bf[4][4];
            #pragma unroll
            for (int ng = 0; ng < 4; ng++) {
                uint32_t baddr = sBimg
                    + (nh * 64 + ng * 16 + ((lane >> 4) << 3) + (lane & 7)) * ROWB
                    + (kk + ((lane >> 3) & 1) * 8) * 2;
                ldsm4(bf[ng], baddr);
            }
            #pragma unroll
            for (int mt = 0; mt < 2; mt++)
                #pragma unroll
                for (int ng = 0; ng < 4; ng++) {
                    mma_bf16(acc[mt][2 * ng],     af[mt], bf[ng][0], bf[ng][1]);
                    mma_bf16(acc[mt][2 * ng + 1], af[mt], bf[ng][2], bf[ng][3]);
                }
        }

        // epilogue: c-frag lane owns rows (l/4, l/4+8), col pair 2(l%4)
        #pragma unroll
        for (int mt = 0; mt < 2; mt++) {
            int r = tb + mt * 16 + (lane >> 2);
            const float* pr0 = pmBase + (size_t)r * DATT;
            const float* pr1 = pr0 + 8 * DATT;
            float s0 = 0.f, s1 = 0.f;
            #pragma unroll
            for (int nt = 0; nt < 8; nt++) {
                int a0 = nh * 64 + nt * 8 + 2 * (lane & 3);
                float2 p0 = *(const float2*)(pr0 + a0);
                float2 p1 = *(const float2*)(pr1 + a0);
                float2 q  = *(const float2*)(s_pq + a0);
                float2 v  = *(const float2*)(s_wv + a0);
                const float* c = acc[mt][nt];
                s0 = fmaf(v.x, tanh_fast(c[0] + q.x + p0.x), s0);
                s0 = fmaf(v.y, tanh_fast(c[1] + q.y + p0.y), s0);
                s1 = fmaf(v.x, tanh_fast(c[2] + q.x + p1.x), s1);
                s1 = fmaf(v.y, tanh_fast(c[3] + q.y + p1.y), s1);
            }
            if (mt == 0) { es00 += s0; es01 += s1; }
            else         { es10 += s0; es11 += s1; }
        }
    }

    // quad reduction (lanes l^1, l^2)
    #pragma unroll
    for (int off = 1; off <= 2; off <<= 1) {
        es00 += __shfl_xor_sync(0xffffffffu, es00, off);
        es01 += __shfl_xor_sync(0xffffffffu, es01, off);
        es10 += __shfl_xor_sync(0xffffffffu, es10, off);
        es11 += __shfl_xor_sync(0xffffffffu, es11, off);
    }
    if ((lane & 3) == 0) {
        int rb = tb + (lane >> 2);
        s_e[rb]      = es00;
        s_e[rb + 8]  = es01;
        s_e[rb + 16] = es10;
        s_e[rb + 24] = es11;
    }
    __syncthreads();
    g_energy[(size_t)b * TT + t0 + tid] = s_e[tid];
}

// ---------------- K2: masked softmax (mask = int32) ----------------
__global__ __launch_bounds__(256) void softmax_kernel(
    const int* __restrict__ mask, float* __restrict__ out_w)
{
    __shared__ float red[32];
    int tid = threadIdx.x, b = blockIdx.x;
    float vals[8];
    float mx = -CUDART_INF_F;
    #pragma unroll
    for (int j = 0; j < 8; j++) {
        int t = tid + j * 256;
        float e = g_energy[(size_t)b * TT + t];
        float v = (mask[(size_t)b * TT + t] != 0) ? -CUDART_INF_F : e;
        vals[j] = v;
        mx = fmaxf(mx, v);
    }
    #pragma unroll
    for (int off = 16; off; off >>= 1) mx = fmaxf(mx, __shfl_xor_sync(0xffffffffu, mx, off));
    if ((tid & 31) == 0) red[tid >> 5] = mx;
    __syncthreads();
    if (tid < 32) {
        float m = (tid < 8) ? red[tid] : -CUDART_INF_F;
        #pragma unroll
        for (int off = 4; off; off >>= 1) m = fmaxf(m, __shfl_xor_sync(0xffffffffu, m, off));
        red[tid] = m;
    }
    __syncthreads();
    mx = red[0];

    float s = 0.f;
    #pragma unroll
    for (int j = 0; j < 8; j++) { float ev = __expf(vals[j] - mx); vals[j] = ev; s += ev; }
    #pragma unroll
    for (int off = 16; off; off >>= 1) s += __shfl_xor_sync(0xffffffffu, s, off);
    __syncthreads();
    if ((tid & 31) == 0) red[tid >> 5] = s;
    __syncthreads();
    if (tid < 32) {
        float m = (tid < 8) ? red[tid] : 0.f;
        #pragma unroll
        for (int off = 4; off; off >>= 1) m += __shfl_xor_sync(0xffffffffu, m, off);
        red[tid] = m;
    }
    __syncthreads();
    float inv = 1.f / red[0];
    #pragma unroll
    for (int j = 0; j < 8; j++) out_w[(size_t)b * TT + tid + j * 256] = vals[j] * inv;
}

// ---------------- K3: context partials ----------------
__global__ __launch_bounds__(128) void context_kernel(
    const float* __restrict__ memory, const float* __restrict__ wgt)
{
    __shared__ float s_w[64];
    int tid = threadIdx.x;
    int b = blockIdx.y, ts = blockIdx.x;
    int t0 = ts * 64;
    if (tid < 64) s_w[tid] = wgt[(size_t)b * TT + t0 + tid];
    __syncthreads();

    const float4* m4 = (const float4*)(memory + ((size_t)b * TT + t0) * DEMB) + tid;
    float4 acc = make_float4(0.f, 0.f, 0.f, 0.f);
    for (int i = 0; i < 64; i += 8) {
        float4 v[8];
        #pragma unroll
        for (int u = 0; u < 8; u++) v[u] = m4[(size_t)(i + u) * 128];
        #pragma unroll
        for (int u = 0; u < 8; u++) {
            float w = s_w[i + u];
            acc.x = fmaf(w, v[u].x, acc.x);
            acc.y = fmaf(w, v[u].y, acc.y);
            acc.z = fmaf(w, v[u].z, acc.z);
            acc.w = fmaf(w, v[u].w, acc.w);
        }
    }
    ((float4*)g_ctx_part)[(size_t)ts * (BB * DEMB / 4) + b * (DEMB / 4) + tid] = acc;
}

// ---------------- K4: reduce context partials ----------------
__global__ __launch_bounds__(256) void reduce_kernel(float* __restrict__ out_ctx)
{
    int i = blockIdx.x * 256 + threadIdx.x;
    float s = 0.f;
    #pragma unroll
    for (int ts = 0; ts < NSPLIT; ts++) s += g_ctx_part[(size_t)ts * BB * DEMB + i];
    out_ctx[i] = s;
}

// ---------------- launch ----------------
extern "C" void kernel_launch(void* const* d_in, const int* in_sizes, int n_in,
                              void* d_out, int out_size)
{
    const float* hidden = (const float*)d_in[0];
    const float* memory = (const float*)d_in[1];
    const float* pm     = (const float*)d_in[2];
    const float* awc    = (const float*)d_in[3];
    const int*   mask   = (const int*)d_in[4];
    const float* Wq     = (const float*)d_in[5];
    const float* Wv     = (const float*)d_in[6];
    const float* convw  = (const float*)d_in[7];
    const float* Wd     = (const float*)d_in[8];

    float* out     = (float*)d_out;
    float* out_ctx = out;                  // [B, 512]
    float* out_w   = out + BB * DEMB;      // [B, T]

    cudaFuncSetAttribute(energy_kernel,
                         cudaFuncAttributeMaxDynamicSharedMemorySize, SM_TOTAL);

    prep_kernel<<<dim3(64, 4), 128>>>(hidden, Wq, convw, Wd);
    dummy_kernel<<<1, 32>>>();
    dummy_kernel<<<1, 32>>>();
    energy_kernel<<<dim3(16, 64), 128, SM_TOTAL>>>(pm, awc, Wv);
    softmax_kernel<<<64, 256>>>(mask, out_w);
    context_kernel<<<dim3(NSPLIT, 64), 128>>>(memory, out_w);
    reduce_kernel<<<128, 256>>>(out_ctx);
}

// round 10
// speedup vs baseline: 1.3340x; 1.2409x over previous
#include <cuda_runtime.h>
#include <cuda_bf16.h>
#include <math_constants.h>
#include <cstdint>

#define BB    64
#define TT    2048
#define DRNN  1024
#define DEMB  512
#define DATT  128
#define NF    32
#define KS    31
#define PADW  15
#define NSPLIT 32

#define KPAD   104
#define ROWB   208

// ---- energy kernel dynamic smem layout (bytes) ----
#define SM_B     0                         // Wd image: 128 x 208 B
#define SM_LOCB  26624                     // loc bf16: 128 x 208 B
#define SM_AW    53248                     // 2*160 floats
#define SM_CW    54528                     // 62*32 floats
#define SM_PQ    62464                     // 128 floats
#define SM_WV    62976                     // 128 floats
#define SM_E     63488                     // 128 floats
#define SM_TOTAL 64000

// ---------------- device scratch ----------------
__device__ float  g_pq[BB * DATT];
__device__ float2 g_cw2[62 * 16];
__device__ unsigned short g_wdbp[128 * KPAD];  // B image [a][k] bf16: Wh|Wh|Wl|0pad
__device__ float  g_energy[BB * TT];
__device__ float  g_ctx_part[NSPLIT * BB * DEMB];

typedef unsigned long long ull;

// ---------------- helpers ----------------
__device__ __forceinline__ ull ffma2u(ull a, ull b, ull c) {
    ull d;
    asm("fma.rn.f32x2 %0, %1, %2, %3;" : "=l"(d) : "l"(a), "l"(b), "l"(c));
    return d;
}
__device__ __forceinline__ ull pack2(float x, float y) {
    ull r; asm("mov.b64 %0, {%1, %2};" : "=l"(r) : "f"(x), "f"(y)); return r;
}
__device__ __forceinline__ float2 unpack2(ull v) {
    float2 f; asm("mov.b64 {%0, %1}, %2;" : "=f"(f.x), "=f"(f.y) : "l"(v)); return f;
}
__device__ __forceinline__ float tanh_fast(float x) {
    float y; asm("tanh.approx.f32 %0, %1;" : "=f"(y) : "f"(x)); return y;
}
__device__ __forceinline__ uint32_t smem_u32(const void* p) {
    uint32_t a;
    asm("{ .reg .u64 t; cvta.to.shared.u64 t, %1; cvt.u32.u64 %0, t; }" : "=r"(a) : "l"(p));
    return a;
}
__device__ __forceinline__ void ldsm4(uint32_t* r, uint32_t addr) {
    asm volatile("ldmatrix.sync.aligned.m8n8.x4.shared.b16 {%0,%1,%2,%3}, [%4];"
        : "=r"(r[0]), "=r"(r[1]), "=r"(r[2]), "=r"(r[3]) : "r"(addr));
}
__device__ __forceinline__ void mma_bf16(float* d, const uint32_t* a,
                                         uint32_t b0, uint32_t b1) {
    asm volatile("mma.sync.aligned.m16n8k16.row.col.f32.bf16.bf16.f32 "
        "{%0,%1,%2,%3}, {%4,%5,%6,%7}, {%8,%9}, {%0,%1,%2,%3};"
        : "+f"(d[0]), "+f"(d[1]), "+f"(d[2]), "+f"(d[3])
        : "r"(a[0]), "r"(a[1]), "r"(a[2]), "r"(a[3]), "r"(b0), "r"(b1));
}

// ---------------- K0: pq GEMM + conv repack + Wd bf16 image ----------------
__global__ __launch_bounds__(128) void prep_kernel(
    const float* __restrict__ hidden, const float* __restrict__ Wq,
    const float* __restrict__ convw,  const float* __restrict__ Wd)
{
    __shared__ float s_h[DRNN];
    int tid = threadIdx.x, b = blockIdx.x, slice = blockIdx.y;
    for (int i = tid; i < DRNN; i += 128) s_h[i] = hidden[(size_t)b * DRNN + i];
    __syncthreads();

    int w = tid >> 5, lane = tid & 31;
    #pragma unroll
    for (int i = 0; i < 8; i++) {
        int a = slice * 32 + w * 8 + i;
        const float* wq = Wq + (size_t)a * DRNN;
        float acc0 = 0.f, acc1 = 0.f;
        #pragma unroll 4
        for (int k = lane; k < DRNN; k += 64) {
            acc0 = fmaf(s_h[k],      wq[k],      acc0);
            acc1 = fmaf(s_h[k + 32], wq[k + 32], acc1);
        }
        float acc = acc0 + acc1;
        #pragma unroll
        for (int off = 16; off; off >>= 1) acc += __shfl_down_sync(0xffffffffu, acc, off);
        if (lane == 0) g_pq[b * DATT + a] = acc;
    }

    if (b == 0 && slice == 0) {
        for (int i = tid; i < 62 * 16; i += 128) {
            int ck = i >> 4, fp = i & 15;
            g_cw2[i] = make_float2(convw[(2 * fp) * 62 + ck], convw[(2 * fp + 1) * 62 + ck]);
        }
    }
    // Wd image build: separate block, thread = a-row, no divisions.
    if (b == 1 && slice == 0) {
        int a = tid;   // only 0..127 used
        if (a < 128) {
            const float* wrow = Wd + a * NF;
            unsigned short* orow = g_wdbp + a * KPAD;
            #pragma unroll 4
            for (int k = 0; k < KPAD; k++) {
                __nv_bfloat16 bv = __float2bfloat16(0.f);
                if (k < 64) {
                    bv = __float2bfloat16(wrow[k & 31]);
                } else if (k < 96) {
                    float orig = wrow[k - 64];
                    float hi = __bfloat162float(__float2bfloat16(orig));
                    bv = __float2bfloat16(orig - hi);
                }
                orow[k] = *(unsigned short*)&bv;
            }
        }
    }
}

__global__ void dummy_kernel() {}

// ---------------- K1: conv + mma.sync paw + tanh + v-dot -> energies ----------------
// 256 threads = 8 warps. Warp w owns m16 tile rows mb=16w..mb+15, all 128 a.
// pm fragments prefetched into registers before the MMA sequence (latency hiding).
__global__ __launch_bounds__(256) void energy_kernel(
    const float* __restrict__ pm, const float* __restrict__ aw,
    const float* __restrict__ wv)
{
    extern __shared__ __align__(16) char smc[];
    float* s_aw = (float*)(smc + SM_AW);
    float* s_cw = (float*)(smc + SM_CW);
    float* s_pq = (float*)(smc + SM_PQ);
    float* s_wv = (float*)(smc + SM_WV);
    float* s_e  = (float*)(smc + SM_E);

    int tid = threadIdx.x;
    int b   = blockIdx.y;
    int t0  = blockIdx.x * 128;
    int w   = tid >> 5, lane = tid & 31;
    uint32_t sbase = smem_u32(smc);

    // ---- stage: B image, conv inputs, pq, wv ----
    {
        const float4* src = (const float4*)g_wdbp;     // 1664 float4
        float4* dst = (float4*)(smc + SM_B);
        for (int i = tid; i < 1664; i += 256) dst[i] = src[i];
    }
    const float* awB = aw + (size_t)b * 2 * TT;
    for (int i = tid; i < 2 * 158; i += 256) {
        int c = i / 158, j = i - c * 158;
        int tg = t0 + j - PADW;
        s_aw[c * 160 + j] = (tg >= 0 && tg < TT) ? awB[(size_t)c * TT + tg] : 0.f;
    }
    {
        const float4* src = (const float4*)g_cw2;      // 496 float4
        float4* dst = (float4*)s_cw;
        for (int i = tid; i < 496; i += 256) dst[i] = src[i];
    }
    if (tid < 128) {
        s_pq[tid] = g_pq[b * DATT + tid];
        s_wv[tid] = wv[tid];
    }
    __syncthreads();

    // ---- conv: thread (tloc = tid&127, fh = tid>>7) -> loc[t][16 filters] ----
    {
        const int tloc = tid & 127, fh = tid >> 7;
        ull cacc[8];
        #pragma unroll
        for (int i = 0; i < 8; i++) cacc[i] = 0ULL;
        #pragma unroll 2
        for (int ck = 0; ck < 62; ck++) {
            int c = (ck >= 31), k = ck - c * 31;
            float av = s_aw[c * 160 + tloc + k];
            ull av2 = pack2(av, av);
            const ulonglong2* row = (const ulonglong2*)(s_cw + ck * 32 + fh * 16);
            #pragma unroll
            for (int q = 0; q < 4; q++) {
                ulonglong2 w2 = row[q];
                cacc[2 * q]     = ffma2u(av2, w2.x, cacc[2 * q]);
                cacc[2 * q + 1] = ffma2u(av2, w2.y, cacc[2 * q + 1]);
            }
        }
        // hi/lo split: segments hi@k=16fh, lo@k=32+16fh, hi@k=64+16fh
        uint32_t awords[24];
        #pragma unroll
        for (int fp = 0; fp < 8; fp++) {
            float2 v = unpack2(cacc[fp]);
            __nv_bfloat16 h0 = __float2bfloat16(v.x), h1 = __float2bfloat16(v.y);
            float r0 = v.x - __bfloat162float(h0);
            float r1 = v.y - __bfloat162float(h1);
            __nv_bfloat16 l0 = __float2bfloat16(r0), l1 = __float2bfloat16(r1);
            uint32_t hw = ((uint32_t)__bfloat16_as_ushort(h1) << 16) | __bfloat16_as_ushort(h0);
            uint32_t lw = ((uint32_t)__bfloat16_as_ushort(l1) << 16) | __bfloat16_as_ushort(l0);
            awords[fp]      = hw;
            awords[8 + fp]  = lw;
            awords[16 + fp] = hw;
        }
        char* base = smc + SM_LOCB + tloc * ROWB + fh * 32;
        #pragma unroll
        for (int sgm = 0; sgm < 3; sgm++) {
            uint4* dst = (uint4*)(base + sgm * 64);
            dst[0] = make_uint4(awords[8 * sgm],     awords[8 * sgm + 1],
                                awords[8 * sgm + 2], awords[8 * sgm + 3]);
            dst[1] = make_uint4(awords[8 * sgm + 4], awords[8 * sgm + 5],
                                awords[8 * sgm + 6], awords[8 * sgm + 7]);
        }
    }
    __syncthreads();

    // ---- per-warp MMA + epilogue (m16 tile rows mb..mb+15) ----
    const int mb = w * 16;
    const uint32_t sLocb = sbase + SM_LOCB;
    const uint32_t sBimg = sbase + SM_B;
    const int r0 = mb + (lane >> 2);
    const float* pr0 = pm + ((size_t)b * TT + t0 + r0) * DATT;
    const float* pr1 = pr0 + 8 * DATT;
    const int ac = 2 * (lane & 3);

    float es0 = 0.f, es1 = 0.f;

    #pragma unroll
    for (int nh = 0; nh < 2; nh++) {
        // prefetch pm fragments for this n-half (independent of MMA -> hides DRAM)
        float2 pv0[8], pv1[8];
        #pragma unroll
        for (int nt = 0; nt < 8; nt++) {
            int a0 = nh * 64 + nt * 8 + ac;
            pv0[nt] = *(const float2*)(pr0 + a0);
            pv1[nt] = *(const float2*)(pr1 + a0);
        }

        float acc[8][4];
        #pragma unroll
        for (int nt = 0; nt < 8; nt++)
            #pragma unroll
            for (int q = 0; q < 4; q++) acc[nt][q] = 0.f;

        #pragma unroll
        for (int ks = 0; ks < 6; ks++) {
            const int kk = ks * 16;
            uint32_t af[4];
            ldsm4(af, sLocb + (mb + (lane & 15)) * ROWB + (kk + (lane >> 4) * 8) * 2);
            uint32_t bf[4][4];
            #pragma unroll
            for (int ng = 0; ng < 4; ng++) {
                uint32_t baddr = sBimg
                    + (nh * 64 + ng * 16 + ((lane >> 4) << 3) + (lane & 7)) * ROWB
                    + (kk + ((lane >> 3) & 1) * 8) * 2;
                ldsm4(bf[ng], baddr);
            }
            #pragma unroll
            for (int ng = 0; ng < 4; ng++) {
                mma_bf16(acc[2 * ng],     af, bf[ng][0], bf[ng][1]);
                mma_bf16(acc[2 * ng + 1], af, bf[ng][2], bf[ng][3]);
            }
        }

        // epilogue: c-frag lane owns rows (r0, r0+8), col pair ac within n-tile
        #pragma unroll
        for (int nt = 0; nt < 8; nt++) {
            int a0 = nh * 64 + nt * 8 + ac;
            float2 q = *(const float2*)(s_pq + a0);
            float2 v = *(const float2*)(s_wv + a0);
            const float* c = acc[nt];
            es0 = fmaf(v.x, tanh_fast(c[0] + q.x + pv0[nt].x), es0);
            es0 = fmaf(v.y, tanh_fast(c[1] + q.y + pv0[nt].y), es0);
            es1 = fmaf(v.x, tanh_fast(c[2] + q.x + pv1[nt].x), es1);
            es1 = fmaf(v.y, tanh_fast(c[3] + q.y + pv1[nt].y), es1);
        }
    }

    // quad reduction (lanes l^1, l^2)
    #pragma unroll
    for (int off = 1; off <= 2; off <<= 1) {
        es0 += __shfl_xor_sync(0xffffffffu, es0, off);
        es1 += __shfl_xor_sync(0xffffffffu, es1, off);
    }
    if ((lane & 3) == 0) {
        s_e[r0]     = es0;
        s_e[r0 + 8] = es1;
    }
    __syncthreads();
    if (tid < 128) g_energy[(size_t)b * TT + t0 + tid] = s_e[tid];
}

// ---------------- K2: masked softmax (mask = int32) ----------------
__global__ __launch_bounds__(256) void softmax_kernel(
    const int* __restrict__ mask, float* __restrict__ out_w)
{
    __shared__ float red[32];
    int tid = threadIdx.x, b = blockIdx.x;
    float vals[8];
    float mx = -CUDART_INF_F;
    #pragma unroll
    for (int j = 0; j < 8; j++) {
        int t = tid + j * 256;
        float e = g_energy[(size_t)b * TT + t];
        float v = (mask[(size_t)b * TT + t] != 0) ? -CUDART_INF_F : e;
        vals[j] = v;
        mx = fmaxf(mx, v);
    }
    #pragma unroll
    for (int off = 16; off; off >>= 1) mx = fmaxf(mx, __shfl_xor_sync(0xffffffffu, mx, off));
    if ((tid & 31) == 0) red[tid >> 5] = mx;
    __syncthreads();
    if (tid < 32) {
        float m = (tid < 8) ? red[tid] : -CUDART_INF_F;
        #pragma unroll
        for (int off = 4; off; off >>= 1) m = fmaxf(m, __shfl_xor_sync(0xffffffffu, m, off));
        red[tid] = m;
    }
    __syncthreads();
    mx = red[0];

    float s = 0.f;
    #pragma unroll
    for (int j = 0; j < 8; j++) { float ev = __expf(vals[j] - mx); vals[j] = ev; s += ev; }
    #pragma unroll
    for (int off = 16; off; off >>= 1) s += __shfl_xor_sync(0xffffffffu, s, off);
    __syncthreads();
    if ((tid & 31) == 0) red[tid >> 5] = s;
    __syncthreads();
    if (tid < 32) {
        float m = (tid < 8) ? red[tid] : 0.f;
        #pragma unroll
        for (int off = 4; off; off >>= 1) m += __shfl_xor_sync(0xffffffffu, m, off);
        red[tid] = m;
    }
    __syncthreads();
    float inv = 1.f / red[0];
    #pragma unroll
    for (int j = 0; j < 8; j++) out_w[(size_t)b * TT + tid + j * 256] = vals[j] * inv;
}

// ---------------- K3: context partials ----------------
__global__ __launch_bounds__(128) void context_kernel(
    const float* __restrict__ memory, const float* __restrict__ wgt)
{
    __shared__ float s_w[64];
    int tid = threadIdx.x;
    int b = blockIdx.y, ts = blockIdx.x;
    int t0 = ts * 64;
    if (tid < 64) s_w[tid] = wgt[(size_t)b * TT + t0 + tid];
    __syncthreads();

    const float4* m4 = (const float4*)(memory + ((size_t)b * TT + t0) * DEMB) + tid;
    float4 acc = make_float4(0.f, 0.f, 0.f, 0.f);
    for (int i = 0; i < 64; i += 8) {
        float4 v[8];
        #pragma unroll
        for (int u = 0; u < 8; u++) v[u] = m4[(size_t)(i + u) * 128];
        #pragma unroll
        for (int u = 0; u < 8; u++) {
            float w = s_w[i + u];
            acc.x = fmaf(w, v[u].x, acc.x);
            acc.y = fmaf(w, v[u].y, acc.y);
            acc.z = fmaf(w, v[u].z, acc.z);
            acc.w = fmaf(w, v[u].w, acc.w);
        }
    }
    ((float4*)g_ctx_part)[(size_t)ts * (BB * DEMB / 4) + b * (DEMB / 4) + tid] = acc;
}

// ---------------- K4: reduce context partials ----------------
__global__ __launch_bounds__(256) void reduce_kernel(float* __restrict__ out_ctx)
{
    int i = blockIdx.x * 256 + threadIdx.x;
    float s = 0.f;
    #pragma unroll
    for (int ts = 0; ts < NSPLIT; ts++) s += g_ctx_part[(size_t)ts * BB * DEMB + i];
    out_ctx[i] = s;
}

// ---------------- launch ----------------
extern "C" void kernel_launch(void* const* d_in, const int* in_sizes, int n_in,
                              void* d_out, int out_size)
{
    const float* hidden = (const float*)d_in[0];
    const float* memory = (const float*)d_in[1];
    const float* pm     = (const float*)d_in[2];
    const float* awc    = (const float*)d_in[3];
    const int*   mask   = (const int*)d_in[4];
    const float* Wq     = (const float*)d_in[5];
    const float* Wv     = (const float*)d_in[6];
    const float* convw  = (const float*)d_in[7];
    const float* Wd     = (const float*)d_in[8];

    float* out     = (float*)d_out;
    float* out_ctx = out;                  // [B, 512]
    float* out_w   = out + BB * DEMB;      // [B, T]

    cudaFuncSetAttribute(energy_kernel,
                         cudaFuncAttributeMaxDynamicSharedMemorySize, SM_TOTAL);

    prep_kernel<<<dim3(64, 4), 128>>>(hidden, Wq, convw, Wd);
    dummy_kernel<<<1, 32>>>();
    dummy_kernel<<<1, 32>>>();
    energy_kernel<<<dim3(16, 64), 256, SM_TOTAL>>>(pm, awc, Wv);
    softmax_kernel<<<64, 256>>>(mask, out_w);
    context_kernel<<<dim3(NSPLIT, 64), 128>>>(memory, out_w);
    reduce_kernel<<<128, 256>>>(out_ctx);
}

// round 11
// speedup vs baseline: 1.4286x; 1.0709x over previous
#include <cuda_runtime.h>
#include <cuda_bf16.h>
#include <math_constants.h>
#include <cstdint>

#define BB    64
#define TT    2048
#define DRNN  1024
#define DEMB  512
#define DATT  128
#define NF    32
#define KS    31
#define PADW  15
#define NSPLIT 16

#define KPAD   104
#define ROWB   208

// ---- energy kernel dynamic smem layout (bytes) ----
#define SM_B     0                         // Wd image: 128 x 208 B
#define SM_LOCB  26624                     // loc bf16: 128 x 208 B
#define SM_AW    53248                     // 2*160 floats
#define SM_CW    54528                     // 62*32 floats
#define SM_PQ    62464                     // 128 floats
#define SM_WV    62976                     // 128 floats
#define SM_E     63488                     // 128 floats
#define SM_TOTAL 64000

// ---------------- device scratch ----------------
__device__ float  g_pq[BB * DATT];
__device__ float2 g_cw2[62 * 16];
__device__ unsigned short g_wdbp[128 * KPAD];  // B image [a][k] bf16: Wh|Wh|Wl|0pad
__device__ float  g_energy[BB * TT];
__device__ float  g_ctx_part[NSPLIT * BB * DEMB];

typedef unsigned long long ull;

// ---------------- helpers ----------------
__device__ __forceinline__ ull ffma2u(ull a, ull b, ull c) {
    ull d;
    asm("fma.rn.f32x2 %0, %1, %2, %3;" : "=l"(d) : "l"(a), "l"(b), "l"(c));
    return d;
}
__device__ __forceinline__ ull pack2(float x, float y) {
    ull r; asm("mov.b64 %0, {%1, %2};" : "=l"(r) : "f"(x), "f"(y)); return r;
}
__device__ __forceinline__ float2 unpack2(ull v) {
    float2 f; asm("mov.b64 {%0, %1}, %2;" : "=f"(f.x), "=f"(f.y) : "l"(v)); return f;
}
__device__ __forceinline__ float tanh_fast(float x) {
    float y; asm("tanh.approx.f32 %0, %1;" : "=f"(y) : "f"(x)); return y;
}
__device__ __forceinline__ uint32_t smem_u32(const void* p) {
    uint32_t a;
    asm("{ .reg .u64 t; cvta.to.shared.u64 t, %1; cvt.u32.u64 %0, t; }" : "=r"(a) : "l"(p));
    return a;
}
__device__ __forceinline__ void ldsm4(uint32_t* r, uint32_t addr) {
    asm volatile("ldmatrix.sync.aligned.m8n8.x4.shared.b16 {%0,%1,%2,%3}, [%4];"
        : "=r"(r[0]), "=r"(r[1]), "=r"(r[2]), "=r"(r[3]) : "r"(addr));
}
__device__ __forceinline__ void mma_bf16(float* d, const uint32_t* a,
                                         uint32_t b0, uint32_t b1) {
    asm volatile("mma.sync.aligned.m16n8k16.row.col.f32.bf16.bf16.f32 "
        "{%0,%1,%2,%3}, {%4,%5,%6,%7}, {%8,%9}, {%0,%1,%2,%3};"
        : "+f"(d[0]), "+f"(d[1]), "+f"(d[2]), "+f"(d[3])
        : "r"(a[0]), "r"(a[1]), "r"(a[2]), "r"(a[3]), "r"(b0), "r"(b1));
}

// ---------------- K0: pq GEMM (16x parallel) + conv repack + Wd bf16 image ----------------
// grid (64, 16): block (b, slice); warp computes 2 a-rows with interleaved loads.
__global__ __launch_bounds__(128) void prep_kernel(
    const float* __restrict__ hidden, const float* __restrict__ Wq,
    const float* __restrict__ convw,  const float* __restrict__ Wd)
{
    __shared__ float s_h[DRNN];
    int tid = threadIdx.x, b = blockIdx.x, slice = blockIdx.y;
    for (int i = tid; i < DRNN; i += 128) s_h[i] = hidden[(size_t)b * DRNN + i];
    __syncthreads();

    int w = tid >> 5, lane = tid & 31;
    int a0 = slice * 8 + w * 2;
    const float* wq0 = Wq + (size_t)a0 * DRNN;
    const float* wq1 = wq0 + DRNN;
    float a00 = 0.f, a01 = 0.f, a10 = 0.f, a11 = 0.f;
    #pragma unroll 4
    for (int k = lane; k < DRNN; k += 64) {
        float h0 = s_h[k], h1 = s_h[k + 32];
        a00 = fmaf(h0, wq0[k],      a00);
        a01 = fmaf(h1, wq0[k + 32], a01);
        a10 = fmaf(h0, wq1[k],      a10);
        a11 = fmaf(h1, wq1[k + 32], a11);
    }
    float rA = a00 + a01, rB = a10 + a11;
    #pragma unroll
    for (int off = 16; off; off >>= 1) {
        rA += __shfl_down_sync(0xffffffffu, rA, off);
        rB += __shfl_down_sync(0xffffffffu, rB, off);
    }
    if (lane == 0) {
        g_pq[b * DATT + a0]     = rA;
        g_pq[b * DATT + a0 + 1] = rB;
    }

    if (b == 0 && slice == 0) {
        for (int i = tid; i < 62 * 16; i += 128) {
            int ck = i >> 4, fp = i & 15;
            g_cw2[i] = make_float2(convw[(2 * fp) * 62 + ck], convw[(2 * fp + 1) * 62 + ck]);
        }
    }
    // Wd image build: separate block, thread = a-row, no divisions.
    if (b == 1 && slice == 0) {
        int a = tid;
        if (a < 128) {
            const float* wrow = Wd + a * NF;
            unsigned short* orow = g_wdbp + a * KPAD;
            #pragma unroll 4
            for (int k = 0; k < KPAD; k++) {
                __nv_bfloat16 bv = __float2bfloat16(0.f);
                if (k < 64) {
                    bv = __float2bfloat16(wrow[k & 31]);
                } else if (k < 96) {
                    float orig = wrow[k - 64];
                    float hi = __bfloat162float(__float2bfloat16(orig));
                    bv = __float2bfloat16(orig - hi);
                }
                orow[k] = *(unsigned short*)&bv;
            }
        }
    }
}

__global__ void dummy_kernel() {}

// ---------------- K1: conv + mma.sync paw + tanh + v-dot -> energies ----------------
// 256 threads = 8 warps. Warp w owns m16 tile rows mb=16w..mb+15, all 128 a.
__global__ __launch_bounds__(256) void energy_kernel(
    const float* __restrict__ pm, const float* __restrict__ aw,
    const float* __restrict__ wv)
{
    extern __shared__ __align__(16) char smc[];
    float* s_aw = (float*)(smc + SM_AW);
    float* s_cw = (float*)(smc + SM_CW);
    float* s_pq = (float*)(smc + SM_PQ);
    float* s_wv = (float*)(smc + SM_WV);
    float* s_e  = (float*)(smc + SM_E);

    int tid = threadIdx.x;
    int b   = blockIdx.y;
    int t0  = blockIdx.x * 128;
    int w   = tid >> 5, lane = tid & 31;
    uint32_t sbase = smem_u32(smc);

    // ---- stage: B image, conv inputs, pq, wv ----
    {
        const float4* src = (const float4*)g_wdbp;     // 1664 float4
        float4* dst = (float4*)(smc + SM_B);
        for (int i = tid; i < 1664; i += 256) dst[i] = src[i];
    }
    const float* awB = aw + (size_t)b * 2 * TT;
    for (int i = tid; i < 2 * 158; i += 256) {
        int c = i / 158, j = i - c * 158;
        int tg = t0 + j - PADW;
        s_aw[c * 160 + j] = (tg >= 0 && tg < TT) ? awB[(size_t)c * TT + tg] : 0.f;
    }
    {
        const float4* src = (const float4*)g_cw2;      // 496 float4
        float4* dst = (float4*)s_cw;
        for (int i = tid; i < 496; i += 256) dst[i] = src[i];
    }
    if (tid < 128) {
        s_pq[tid] = g_pq[b * DATT + tid];
        s_wv[tid] = wv[tid];
    }
    __syncthreads();

    // ---- conv: thread (tloc = tid&127, fh = tid>>7) -> loc[t][16 filters] ----
    {
        const int tloc = tid & 127, fh = tid >> 7;
        ull cacc[8];
        #pragma unroll
        for (int i = 0; i < 8; i++) cacc[i] = 0ULL;
        #pragma unroll 2
        for (int ck = 0; ck < 62; ck++) {
            int c = (ck >= 31), k = ck - c * 31;
            float av = s_aw[c * 160 + tloc + k];
            ull av2 = pack2(av, av);
            const ulonglong2* row = (const ulonglong2*)(s_cw + ck * 32 + fh * 16);
            #pragma unroll
            for (int q = 0; q < 4; q++) {
                ulonglong2 w2 = row[q];
                cacc[2 * q]     = ffma2u(av2, w2.x, cacc[2 * q]);
                cacc[2 * q + 1] = ffma2u(av2, w2.y, cacc[2 * q + 1]);
            }
        }
        // hi/lo split: segments hi@k=16fh, lo@k=32+16fh, hi@k=64+16fh
        uint32_t awords[24];
        #pragma unroll
        for (int fp = 0; fp < 8; fp++) {
            float2 v = unpack2(cacc[fp]);
            __nv_bfloat16 h0 = __float2bfloat16(v.x), h1 = __float2bfloat16(v.y);
            float r0 = v.x - __bfloat162float(h0);
            float r1 = v.y - __bfloat162float(h1);
            __nv_bfloat16 l0 = __float2bfloat16(r0), l1 = __float2bfloat16(r1);
            uint32_t hw = ((uint32_t)__bfloat16_as_ushort(h1) << 16) | __bfloat16_as_ushort(h0);
            uint32_t lw = ((uint32_t)__bfloat16_as_ushort(l1) << 16) | __bfloat16_as_ushort(l0);
            awords[fp]      = hw;
            awords[8 + fp]  = lw;
            awords[16 + fp] = hw;
        }
        char* base = smc + SM_LOCB + tloc * ROWB + fh * 32;
        #pragma unroll
        for (int sgm = 0; sgm < 3; sgm++) {
            uint4* dst = (uint4*)(base + sgm * 64);
            dst[0] = make_uint4(awords[8 * sgm],     awords[8 * sgm + 1],
                                awords[8 * sgm + 2], awords[8 * sgm + 3]);
            dst[1] = make_uint4(awords[8 * sgm + 4], awords[8 * sgm + 5],
                                awords[8 * sgm + 6], awords[8 * sgm + 7]);
        }
    }
    __syncthreads();

    // ---- per-warp MMA + epilogue (m16 tile rows mb..mb+15) ----
    const int mb = w * 16;
    const uint32_t sLocb = sbase + SM_LOCB;
    const uint32_t sBimg = sbase + SM_B;
    const int r0 = mb + (lane >> 2);
    const float* pr0 = pm + ((size_t)b * TT + t0 + r0) * DATT;
    const float* pr1 = pr0 + 8 * DATT;
    const int ac = 2 * (lane & 3);

    float es0 = 0.f, es1 = 0.f;

    #pragma unroll
    for (int nh = 0; nh < 2; nh++) {
        // prefetch pm fragments for this n-half (independent of MMA -> hides DRAM)
        float2 pv0[8], pv1[8];
        #pragma unroll
        for (int nt = 0; nt < 8; nt++) {
            int a0 = nh * 64 + nt * 8 + ac;
            pv0[nt] = *(const float2*)(pr0 + a0);
            pv1[nt] = *(const float2*)(pr1 + a0);
        }

        float acc[8][4];
        #pragma unroll
        for (int nt = 0; nt < 8; nt++)
            #pragma unroll
            for (int q = 0; q < 4; q++) acc[nt][q] = 0.f;

        #pragma unroll
        for (int ks = 0; ks < 6; ks++) {
            const int kk = ks * 16;
            uint32_t af[4];
            ldsm4(af, sLocb + (mb + (lane & 15)) * ROWB + (kk + (lane >> 4) * 8) * 2);
            uint32_t bf[4][4];
            #pragma unroll
            for (int ng = 0; ng < 4; ng++) {
                uint32_t baddr = sBimg
                    + (nh * 64 + ng * 16 + ((lane >> 4) << 3) + (lane & 7)) * ROWB
                    + (kk + ((lane >> 3) & 1) * 8) * 2;
                ldsm4(bf[ng], baddr);
            }
            #pragma unroll
            for (int ng = 0; ng < 4; ng++) {
                mma_bf16(acc[2 * ng],     af, bf[ng][0], bf[ng][1]);
                mma_bf16(acc[2 * ng + 1], af, bf[ng][2], bf[ng][3]);
            }
        }

        // epilogue: c-frag lane owns rows (r0, r0+8), col pair ac within n-tile
        #pragma unroll
        for (int nt = 0; nt < 8; nt++) {
            int a0 = nh * 64 + nt * 8 + ac;
            float2 q = *(const float2*)(s_pq + a0);
            float2 v = *(const float2*)(s_wv + a0);
            const float* c = acc[nt];
            es0 = fmaf(v.x, tanh_fast(c[0] + q.x + pv0[nt].x), es0);
            es0 = fmaf(v.y, tanh_fast(c[1] + q.y + pv0[nt].y), es0);
            es1 = fmaf(v.x, tanh_fast(c[2] + q.x + pv1[nt].x), es1);
            es1 = fmaf(v.y, tanh_fast(c[3] + q.y + pv1[nt].y), es1);
        }
    }

    // quad reduction (lanes l^1, l^2)
    #pragma unroll
    for (int off = 1; off <= 2; off <<= 1) {
        es0 += __shfl_xor_sync(0xffffffffu, es0, off);
        es1 += __shfl_xor_sync(0xffffffffu, es1, off);
    }
    if ((lane & 3) == 0) {
        s_e[r0]     = es0;
        s_e[r0 + 8] = es1;
    }
    __syncthreads();
    if (tid < 128) g_energy[(size_t)b * TT + t0 + tid] = s_e[tid];
}

// ---------------- K2: masked softmax (mask = int32) ----------------
__global__ __launch_bounds__(256) void softmax_kernel(
    const int* __restrict__ mask, float* __restrict__ out_w)
{
    __shared__ float red[32];
    int tid = threadIdx.x, b = blockIdx.x;
    float vals[8];
    float mx = -CUDART_INF_F;
    #pragma unroll
    for (int j = 0; j < 8; j++) {
        int t = tid + j * 256;
        float e = g_energy[(size_t)b * TT + t];
        float v = (mask[(size_t)b * TT + t] != 0) ? -CUDART_INF_F : e;
        vals[j] = v;
        mx = fmaxf(mx, v);
    }
    #pragma unroll
    for (int off = 16; off; off >>= 1) mx = fmaxf(mx, __shfl_xor_sync(0xffffffffu, mx, off));
    if ((tid & 31) == 0) red[tid >> 5] = mx;
    __syncthreads();
    if (tid < 32) {
        float m = (tid < 8) ? red[tid] : -CUDART_INF_F;
        #pragma unroll
        for (int off = 4; off; off >>= 1) m = fmaxf(m, __shfl_xor_sync(0xffffffffu, m, off));
        red[tid] = m;
    }
    __syncthreads();
    mx = red[0];

    float s = 0.f;
    #pragma unroll
    for (int j = 0; j < 8; j++) { float ev = __expf(vals[j] - mx); vals[j] = ev; s += ev; }
    #pragma unroll
    for (int off = 16; off; off >>= 1) s += __shfl_xor_sync(0xffffffffu, s, off);
    __syncthreads();
    if ((tid & 31) == 0) red[tid >> 5] = s;
    __syncthreads();
    if (tid < 32) {
        float m = (tid < 8) ? red[tid] : 0.f;
        #pragma unroll
        for (int off = 4; off; off >>= 1) m += __shfl_xor_sync(0xffffffffu, m, off);
        red[tid] = m;
    }
    __syncthreads();
    float inv = 1.f / red[0];
    #pragma unroll
    for (int j = 0; j < 8; j++) out_w[(size_t)b * TT + tid + j * 256] = vals[j] * inv;
}

// ---------------- K3: context partials (MLP=16 batched loads) ----------------
__global__ __launch_bounds__(128) void context_kernel(
    const float* __restrict__ memory, const float* __restrict__ wgt)
{
    __shared__ float s_w[128];
    int tid = threadIdx.x;
    int b = blockIdx.y, ts = blockIdx.x;
    int t0 = ts * 128;
    s_w[tid] = wgt[(size_t)b * TT + t0 + tid];
    __syncthreads();

    const float4* m4 = (const float4*)(memory + ((size_t)b * TT + t0) * DEMB) + tid;
    float4 acc = make_float4(0.f, 0.f, 0.f, 0.f);
    for (int i = 0; i < 128; i += 16) {
        float4 v[16];
        #pragma unroll
        for (int u = 0; u < 16; u++) v[u] = m4[(size_t)(i + u) * 128];
        #pragma unroll
        for (int u = 0; u < 16; u++) {
            float w = s_w[i + u];
            acc.x = fmaf(w, v[u].x, acc.x);
            acc.y = fmaf(w, v[u].y, acc.y);
            acc.z = fmaf(w, v[u].z, acc.z);
            acc.w = fmaf(w, v[u].w, acc.w);
        }
    }
    ((float4*)g_ctx_part)[(size_t)ts * (BB * DEMB / 4) + b * (DEMB / 4) + tid] = acc;
}

// ---------------- K4: reduce context partials ----------------
__global__ __launch_bounds__(256) void reduce_kernel(float* __restrict__ out_ctx)
{
    int i = blockIdx.x * 256 + threadIdx.x;
    float s = 0.f;
    #pragma unroll
    for (int ts = 0; ts < NSPLIT; ts++) s += g_ctx_part[(size_t)ts * BB * DEMB + i];
    out_ctx[i] = s;
}

// ---------------- launch ----------------
extern "C" void kernel_launch(void* const* d_in, const int* in_sizes, int n_in,
                              void* d_out, int out_size)
{
    const float* hidden = (const float*)d_in[0];
    const float* memory = (const float*)d_in[1];
    const float* pm     = (const float*)d_in[2];
    const float* awc    = (const float*)d_in[3];
    const int*   mask   = (const int*)d_in[4];
    const float* Wq     = (const float*)d_in[5];
    const float* Wv     = (const float*)d_in[6];
    const float* convw  = (const float*)d_in[7];
    const float* Wd     = (const float*)d_in[8];

    float* out     = (float*)d_out;
    float* out_ctx = out;                  // [B, 512]
    float* out_w   = out + BB * DEMB;      // [B, T]

    cudaFuncSetAttribute(energy_kernel,
                         cudaFuncAttributeMaxDynamicSharedMemorySize, SM_TOTAL);

    prep_kernel<<<dim3(64, 16), 128>>>(hidden, Wq, convw, Wd);
    dummy_kernel<<<1, 32>>>();
    dummy_kernel<<<1, 32>>>();
    energy_kernel<<<dim3(16, 64), 256, SM_TOTAL>>>(pm, awc, Wv);
    softmax_kernel<<<64, 256>>>(mask, out_w);
    context_kernel<<<dim3(NSPLIT, 64), 128>>>(memory, out_w);
    reduce_kernel<<<128, 256>>>(out_ctx);
}